// round 3
// baseline (speedup 1.0000x reference)
#include <cuda_runtime.h>
#include <cuda_bf16.h>

// DCT-II coefficients: A = 1/sqrt(8), Ck = 0.5*cos(k*pi/16)
#define CA 0.35355339059327373f
#define K1 0.4903926402016152f
#define K2 0.46193976625564337f
#define K3 0.4157348061512726f
#define K5 0.27778511650980114f
#define K6 0.19134171618254492f
#define K7 0.09754516100806417f

// invQ[k][l] = 100 / LUMINANCE_QUANTIZATION_TABLE[k][l]
__constant__ float INVQ[64] = {
    100.0f/16.0f, 100.0f/11.0f, 100.0f/10.0f, 100.0f/16.0f, 100.0f/24.0f, 100.0f/40.0f,  100.0f/51.0f,  100.0f/61.0f,
    100.0f/12.0f, 100.0f/12.0f, 100.0f/14.0f, 100.0f/19.0f, 100.0f/26.0f, 100.0f/58.0f,  100.0f/60.0f,  100.0f/55.0f,
    100.0f/14.0f, 100.0f/13.0f, 100.0f/16.0f, 100.0f/24.0f, 100.0f/40.0f, 100.0f/57.0f,  100.0f/69.0f,  100.0f/56.0f,
    100.0f/14.0f, 100.0f/17.0f, 100.0f/22.0f, 100.0f/29.0f, 100.0f/51.0f, 100.0f/87.0f,  100.0f/80.0f,  100.0f/62.0f,
    100.0f/18.0f, 100.0f/22.0f, 100.0f/37.0f, 100.0f/56.0f, 100.0f/68.0f, 100.0f/109.0f, 100.0f/103.0f, 100.0f/77.0f,
    100.0f/24.0f, 100.0f/36.0f, 100.0f/55.0f, 100.0f/64.0f, 100.0f/81.0f, 100.0f/104.0f, 100.0f/113.0f, 100.0f/92.0f,
    100.0f/49.0f, 100.0f/64.0f, 100.0f/78.0f, 100.0f/87.0f, 100.0f/103.0f,100.0f/121.0f, 100.0f/120.0f, 100.0f/101.0f,
    100.0f/72.0f, 100.0f/92.0f, 100.0f/95.0f, 100.0f/98.0f, 100.0f/112.0f,100.0f/100.0f, 100.0f/103.0f, 100.0f/99.0f
};

// 8-point orthonormal DCT-II via even/odd butterfly (36 ops vs 64 FMA direct).
// C[k][n] = +/-C[k][7-n] (even k symmetric, odd k antisymmetric).
__device__ __forceinline__ void dct8(const float* __restrict__ x, float* __restrict__ y) {
    float s0 = x[0] + x[7], s1 = x[1] + x[6], s2 = x[2] + x[5], s3 = x[3] + x[4];
    float d0 = x[0] - x[7], d1 = x[1] - x[6], d2 = x[2] - x[5], d3 = x[3] - x[4];
    float e0 = s0 + s3, e1 = s1 + s2;
    float f0 = s0 - s3, f1 = s1 - s2;
    y[0] = CA * (e0 + e1);
    y[4] = CA * (e0 - e1);
    y[2] = K2 * f0 + K6 * f1;
    y[6] = K6 * f0 - K2 * f1;
    y[1] = K1 * d0 + K3 * d1 + K5 * d2 + K7 * d3;
    y[3] = K3 * d0 - K7 * d1 - K1 * d2 - K5 * d3;
    y[5] = K5 * d0 - K1 * d1 + K7 * d2 + K3 * d3;
    y[7] = K7 * d0 - K5 * d1 + K3 * d2 - K1 * d3;
}

// One thread = one 8x8 block. 16 batches * 128 hb * 128 wb = 262144 threads.
// tid layout: wb fastest (coalesced loads AND stores), then hb, then b.
__global__ __launch_bounds__(128) void jpeg_dct_kernel(
    const float* __restrict__ img,   // [16, 1, 1024, 1024]
    const float* __restrict__ qf,    // [16]
    float* __restrict__ out)         // [16, 64, 128, 128]
{
    const int tid = blockIdx.x * 128 + threadIdx.x;
    const int wb = tid & 127;
    const int hb = (tid >> 7) & 127;
    const int b  = tid >> 14;

    // input base: b*1024*1024 + (hb*8)*1024 + wb*8
    const float* p = img + ((size_t)b << 20) + ((size_t)hb << 13) + (wb << 3);

    float X[8][8];
#pragma unroll
    for (int r = 0; r < 8; r++) {
        float4 v0 = *reinterpret_cast<const float4*>(p + ((size_t)r << 10));
        float4 v1 = *reinterpret_cast<const float4*>(p + ((size_t)r << 10) + 4);
        X[r][0] = v0.x; X[r][1] = v0.y; X[r][2] = v0.z; X[r][3] = v0.w;
        X[r][4] = v1.x; X[r][5] = v1.y; X[r][6] = v1.z; X[r][7] = v1.w;
    }

    // Row pass: T[r][l] = sum_n X[r][n] * C[l][n]
    float T[8][8];
#pragma unroll
    for (int r = 0; r < 8; r++) dct8(X[r], T[r]);

    // Column pass: Y[k][l] = sum_r C[k][r] * T[r][l]
    float Y[8][8];
#pragma unroll
    for (int l = 0; l < 8; l++) {
        float col[8], res[8];
#pragma unroll
        for (int r = 0; r < 8; r++) col[r] = T[r][l];
        dct8(col, res);
#pragma unroll
        for (int k = 0; k < 8; k++) Y[k][l] = res[k];
    }

    // The -128 centering only affects the DC term: C@(128*J)@C^T = 1024 * e00.
    Y[0][0] -= 1024.0f;

    // quality factor -> inverse scale (one RCP at most, per thread)
    float q = qf[b];
    float invf = (q < 50.0f) ? (q * 2.0e-4f) : (1.0f / (200.0f - 2.0f * q));

    // output base: b*64*16384 + hb*128 + wb ; plane stride 16384
    float* o = out + ((size_t)b << 20) + (hb << 7) + wb;
#pragma unroll
    for (int kl = 0; kl < 64; kl++) {
        o[(size_t)kl << 14] = Y[kl >> 3][kl & 7] * (INVQ[kl] * invf);
    }
}

extern "C" void kernel_launch(void* const* d_in, const int* in_sizes, int n_in,
                              void* d_out, int out_size) {
    const float* img = (const float*)d_in[0];
    const float* qf  = (const float*)d_in[1];
    float* out = (float*)d_out;
    jpeg_dct_kernel<<<2048, 128>>>(img, qf, out);
}